// round 5
// baseline (speedup 1.0000x reference)
#include <cuda_runtime.h>
#include <cstdint>

// TensorizedEmbedding: vocab=32000=(8,10,20,20), out=768=(4,4,6,8), ranks (1,16,16,16,1)
// Split TT-chain in the middle:
//   a = idx / 400 in [0,80)   -> T01[a] : [16 r2][16 m01-permuted]   (80 KB, L1-hot)
//   b = idx % 400 in [0,400)  -> T23[b] : [16 r2][48 m23]            (1.2 MB, L2)
// ~82 tokens share each b -> bin tokens by b, stage T23[b] in smem once per block.

#define NTOK_MAX 65536
#define NBIN 400
#define SPLIT 2          // blocks per bin in main kernel (load balance)

__device__ float g_T01[80 * 256];     // [a][r2][m01p], m01p = (m1<<2)|m0
__device__ float g_T23[NBIN * 768];   // [b][r2][m23]
__device__ int   g_count[NBIN];
__device__ int   g_cursor[NBIN];
__device__ int   g_binstart[NBIN + 1];
__device__ int   g_perm[NTOK_MAX];    // packed: t | (a<<16)

// ---------------------------------------------------------------------------
// Fused precompute (also zeroes histogram counters for this launch).
__global__ void precompute_tables(const float* __restrict__ core0,
                                  const float* __restrict__ core1,
                                  const float* __restrict__ core2,
                                  const float* __restrict__ core3) {
    int i = blockIdx.x * blockDim.x + threadIdx.x;
    if (i < NBIN) g_count[i] = 0;
    if (i < NBIN * 768) {
        // T23[b][r2][m23] = sum_r3 core2[r2][d2][m2][r3] * core3[r3][d3][m3]
        int b = i / 768;
        int e = i - b * 768;
        int r2  = e / 48;
        int m23 = e - r2 * 48;
        int m2 = m23 >> 3, m3 = m23 & 7;
        int d2 = b / 20;
        int d3 = b - d2 * 20;
        float s = 0.f;
#pragma unroll
        for (int r3 = 0; r3 < 16; ++r3) {
            float c2 = __ldg(core2 + (((r2 * 20 + d2) * 6 + m2) * 16 + r3));
            float c3 = __ldg(core3 + ((r3 * 20 + d3) * 8 + m3));
            s = fmaf(c2, c3, s);
        }
        g_T23[i] = s;
    } else if (i < NBIN * 768 + 80 * 256) {
        // T01[a][r2][m01] = sum_r1 core0[0][d0][m0][r1] * core1[r1][d1][m1][r2]
        int j = i - NBIN * 768;
        int a = j >> 8;
        int e = j & 255;
        int r2  = e & 15;
        int m01 = e >> 4;
        int m0 = m01 >> 2, m1 = m01 & 3;
        int d0 = a / 10;
        int d1 = a - d0 * 10;
        float s = 0.f;
#pragma unroll
        for (int r1 = 0; r1 < 16; ++r1) {
            float c0 = __ldg(core0 + ((d0 * 4 + m0) * 16 + r1));
            float c1 = __ldg(core1 + (((r1 * 10 + d1) * 4 + m1) * 16 + r2));
            s = fmaf(c0, c1, s);
        }
        int m01p = (m1 << 2) | m0;     // 4x4 transpose permutation
        g_T01[a * 256 + r2 * 16 + m01p] = s;
    }
}

// ---------------------------------------------------------------------------
__global__ void hist_kernel(const int* __restrict__ x, int ntok) {
    int t = blockIdx.x * blockDim.x + threadIdx.x;
    if (t < ntok) {
        int idx = __ldg(x + t);
        atomicAdd(&g_count[idx % NBIN], 1);
    }
}

// Single-block exclusive scan over 400 bins (Hillis-Steele, 512 threads).
__global__ void scan_kernel(int ntok) {
    __shared__ int s[512];
    int i = threadIdx.x;
    int c = (i < NBIN) ? g_count[i] : 0;
    s[i] = c;
    __syncthreads();
#pragma unroll
    for (int off = 1; off < 512; off <<= 1) {
        int v = (i >= off) ? s[i - off] : 0;
        __syncthreads();
        s[i] += v;
        __syncthreads();
    }
    if (i < NBIN) {
        int excl = s[i] - c;
        g_binstart[i] = excl;
        g_cursor[i]   = excl;
    }
    if (i == NBIN) g_binstart[NBIN] = ntok;
}

__global__ void scatter_kernel(const int* __restrict__ x, int ntok) {
    int t = blockIdx.x * blockDim.x + threadIdx.x;
    if (t < ntok) {
        int idx = __ldg(x + t);
        int a = idx / NBIN;
        int b = idx - a * NBIN;
        int pos = atomicAdd(&g_cursor[b], 1);
        g_perm[pos] = t | (a << 16);       // t < 65536, a < 80
    }
}

// ---------------------------------------------------------------------------
// Main: SPLIT blocks per bin. Stage T23[b] into smem with 12-float group
// stride (bank-conflict-free for the float4+float2 lane loads), then each
// warp processes tokens of this bin. Lane tile: g01=lane>>3, g23=lane&7;
// acc[i][*] = output row 4i+g01, cols g23*6..+6 (stores 768B-coalesced).
__global__ void __launch_bounds__(256)
tte_binned(float* __restrict__ out) {
    __shared__ __align__(16) float sT23[16 * 96];   // [r2][g23*12 + w], w<6 used
    int b    = blockIdx.x / SPLIT;
    int half = blockIdx.x - b * SPLIT;
    int tid  = threadIdx.x;

    for (int j = tid; j < 768; j += 256) {
        float v = g_T23[b * 768 + j];
        int r2  = j / 48;
        int m23 = j - r2 * 48;
        int g   = m23 / 6;
        int w   = m23 - g * 6;
        sT23[r2 * 96 + g * 12 + w] = v;
    }
    __syncthreads();

    int start = g_binstart[b];
    int end   = g_binstart[b + 1];
    int warp  = tid >> 5;
    int lane  = tid & 31;
    int g01   = lane >> 3;
    int g23   = lane & 7;
    const float* t23s = sT23 + g23 * 12;

    for (int j = start + half * 8 + warp; j < end; j += 8 * SPLIT) {
        int packed = g_perm[j];
        int t = packed & 0xFFFF;
        int a = packed >> 16;
        const float* t01p = g_T01 + a * 256 + g01 * 4;

        float acc[4][6];
#pragma unroll
        for (int i = 0; i < 4; ++i)
#pragma unroll
            for (int k = 0; k < 6; ++k) acc[i][k] = 0.f;

#pragma unroll
        for (int r2 = 0; r2 < 16; ++r2) {
            float4 p  = __ldg((const float4*)(t01p + r2 * 16));
            float4 q4 = *(const float4*)(t23s + r2 * 96);
            float2 q2 = *(const float2*)(t23s + r2 * 96 + 4);
            float pp[4] = {p.x, p.y, p.z, p.w};
            float qq[6] = {q4.x, q4.y, q4.z, q4.w, q2.x, q2.y};
#pragma unroll
            for (int i = 0; i < 4; ++i)
#pragma unroll
                for (int k = 0; k < 6; ++k)
                    acc[i][k] = fmaf(pp[i], qq[k], acc[i][k]);
        }

        float* o = out + (size_t)t * 768 + g23 * 6;
#pragma unroll
        for (int i = 0; i < 4; ++i) {
            float* orow = o + (i * 4 + g01) * 48;
            *(float2*)(orow)     = make_float2(acc[i][0], acc[i][1]);
            *(float2*)(orow + 2) = make_float2(acc[i][2], acc[i][3]);
            *(float2*)(orow + 4) = make_float2(acc[i][4], acc[i][5]);
        }
    }
}

// ---------------------------------------------------------------------------
extern "C" void kernel_launch(void* const* d_in, const int* in_sizes, int n_in,
                              void* d_out, int out_size) {
    const int*   x     = (const int*)d_in[0];
    const float* core0 = (const float*)d_in[1];
    const float* core1 = (const float*)d_in[2];
    const float* core2 = (const float*)d_in[3];
    const float* core3 = (const float*)d_in[4];
    float* out = (float*)d_out;

    int ntok = in_sizes[0];   // 32768

    int pre_total = NBIN * 768 + 80 * 256;
    precompute_tables<<<(pre_total + 255) / 256, 256>>>(core0, core1, core2, core3);
    hist_kernel<<<(ntok + 255) / 256, 256>>>(x, ntok);
    scan_kernel<<<1, 512>>>(ntok);
    scatter_kernel<<<(ntok + 255) / 256, 256>>>(x, ntok);
    tte_binned<<<NBIN * SPLIT, 256>>>(out);
}

// round 7
// speedup vs baseline: 1.0677x; 1.0677x over previous
#include <cuda_runtime.h>
#include <cstdint>

// TensorizedEmbedding: vocab=32000=(8,10,20,20), out=768=(4,4,6,8), ranks (1,16,16,16,1)
// Split TT-chain in the middle:
//   a = idx / 400 in [0,80)   -> T01[a] : [16 r2][16 m01-permuted]   (80 KB, L1-hot)
//   b = idx % 400 in [0,400)  -> T23[b] : [16 r2][48 m23] dense      (1.2 MB, L2)
//
// Main kernel: 1 block = 4 tokens, 2 warps per token (rows split by warp
// parity h). Each token's 3KB T23 panel is staged to smem ONCE (coalesced
// float4 loads), inner loop is LDS-only for T23 (29cyc vs ~250cyc L2).
// Lane tile 2x6 -> 12 accumulators -> low regs -> high occupancy.

__device__ __align__(16) float g_T01[80 * 256];   // [a][r2][m01p], m01p=(m1<<2)|m0
__device__ __align__(16) float g_T23[400 * 768];  // [b][r2][m23] dense

// ---------------------------------------------------------------------------
// Fused precompute of both tables.
__global__ void precompute_tables(const float* __restrict__ core0,
                                  const float* __restrict__ core1,
                                  const float* __restrict__ core2,
                                  const float* __restrict__ core3) {
    int i = blockIdx.x * blockDim.x + threadIdx.x;
    if (i < 400 * 768) {
        // T23[b][r2][m23] = sum_r3 core2[r2][d2][m2][r3] * core3[r3][d3][m3]
        int b = i / 768;
        int e = i - b * 768;
        int r2  = e / 48;
        int m23 = e - r2 * 48;
        int m2 = m23 >> 3, m3 = m23 & 7;
        int d2 = b / 20;
        int d3 = b - d2 * 20;
        float s = 0.f;
#pragma unroll
        for (int r3 = 0; r3 < 16; ++r3) {
            float c2 = __ldg(core2 + (((r2 * 20 + d2) * 6 + m2) * 16 + r3));
            float c3 = __ldg(core3 + ((r3 * 20 + d3) * 8 + m3));
            s = fmaf(c2, c3, s);
        }
        g_T23[i] = s;
    } else if (i < 400 * 768 + 80 * 256) {
        // T01[a][r2][m01] = sum_r1 core0[0][d0][m0][r1] * core1[r1][d1][m1][r2]
        int j = i - 400 * 768;
        int a = j >> 8;
        int e = j & 255;
        int r2  = e & 15;
        int m01 = e >> 4;
        int m0 = m01 >> 2, m1 = m01 & 3;
        int d0 = a / 10;
        int d1 = a - d0 * 10;
        float s = 0.f;
#pragma unroll
        for (int r1 = 0; r1 < 16; ++r1) {
            float c0 = __ldg(core0 + ((d0 * 4 + m0) * 16 + r1));
            float c1 = __ldg(core1 + (((r1 * 10 + d1) * 4 + m1) * 16 + r2));
            s = fmaf(c0, c1, s);
        }
        int m01p = (m1 << 2) | m0;     // 4x4 transpose permutation
        g_T01[a * 256 + r2 * 16 + m01p] = s;
    }
}

// ---------------------------------------------------------------------------
// smem T23 layout per token: [r2][g23*12 + w], w<6 used. Lane g23 groups are
// 48B apart -> LDS.128/LDS.64 conflict-free across the 8 groups.
__global__ void __launch_bounds__(256)
tte_main(const int* __restrict__ x, float* __restrict__ out, int ntok) {
    __shared__ __align__(16) float sT23[4 * 16 * 96];   // 4 tokens * 6KB = 24KB
    int tid    = threadIdx.x;
    int t_base = blockIdx.x * 4;

    // Stage: 768 float4 (4 tokens x 192) across 256 threads, 3 each.
    for (int k = tid; k < 768; k += 256) {
        int lt = k / 192;                 // local token 0..3
        int t  = t_base + lt;
        if (t < ntok) {
            int idxv = __ldg(x + t);
            int b = idxv % 400;
            int j4 = k - lt * 192;
            float4 v = __ldg((const float4*)(g_T23 + b * 768 + j4 * 4));
            int j  = j4 * 4;
            int r2 = j / 48;              // 48 % 4 == 0 -> same r2 for all 4
            int base = lt * 1536 + r2 * 96;
            float vv[4] = {v.x, v.y, v.z, v.w};
#pragma unroll
            for (int e = 0; e < 4; ++e) {
                int m23 = j + e - r2 * 48;
                int g = m23 / 6;
                int w = m23 - g * 6;
                sT23[base + g * 12 + w] = vv[e];
            }
        }
    }
    __syncthreads();

    int warp = tid >> 5;
    int lane = tid & 31;
    int lt   = warp >> 1;    // local token
    int h    = warp & 1;     // row half
    int t    = t_base + lt;
    if (t >= ntok) return;

    int idxv = __ldg(x + t);
    int a = idxv / 400;

    int g01 = lane >> 3;     // 0..3
    int g23 = lane & 7;      // 0..7

    // T01 float2 at m01p position g01*4 + 2h -> rows 8h+g01 and 8h+4+g01
    const float* __restrict__ t01p = g_T01 + a * 256 + g01 * 4 + 2 * h;
    const float* t23s = sT23 + lt * 1536 + g23 * 12;

    float acc0[6], acc1[6];
#pragma unroll
    for (int k = 0; k < 6; ++k) { acc0[k] = 0.f; acc1[k] = 0.f; }

#pragma unroll
    for (int r2 = 0; r2 < 16; ++r2) {
        float2 p  = __ldg((const float2*)(t01p + r2 * 16));
        float4 q4 = *(const float4*)(t23s + r2 * 96);
        float2 q2 = *(const float2*)(t23s + r2 * 96 + 4);
        float qq[6] = {q4.x, q4.y, q4.z, q4.w, q2.x, q2.y};
#pragma unroll
        for (int k = 0; k < 6; ++k) {
            acc0[k] = fmaf(p.x, qq[k], acc0[k]);
            acc1[k] = fmaf(p.y, qq[k], acc1[k]);
        }
    }

    // Stores: warp writes rows {8h..8h+3} and {8h+4..8h+7}; each round is a
    // contiguous 768B warp write.
    float* o  = out + (size_t)t * 768 + g23 * 6;
    float* r0 = o + (8 * h + g01) * 48;
    float* r1 = o + (8 * h + 4 + g01) * 48;
    *(float2*)(r0)     = make_float2(acc0[0], acc0[1]);
    *(float2*)(r0 + 2) = make_float2(acc0[2], acc0[3]);
    *(float2*)(r0 + 4) = make_float2(acc0[4], acc0[5]);
    *(float2*)(r1)     = make_float2(acc1[0], acc1[1]);
    *(float2*)(r1 + 2) = make_float2(acc1[2], acc1[3]);
    *(float2*)(r1 + 4) = make_float2(acc1[4], acc1[5]);
}

// ---------------------------------------------------------------------------
extern "C" void kernel_launch(void* const* d_in, const int* in_sizes, int n_in,
                              void* d_out, int out_size) {
    const int*   x     = (const int*)d_in[0];
    const float* core0 = (const float*)d_in[1];
    const float* core1 = (const float*)d_in[2];
    const float* core2 = (const float*)d_in[3];
    const float* core3 = (const float*)d_in[4];
    float* out = (float*)d_out;

    int ntok = in_sizes[0];   // 32768

    int pre_total = 400 * 768 + 80 * 256;
    precompute_tables<<<(pre_total + 255) / 256, 256>>>(core0, core1, core2, core3);

    int grid = (ntok + 3) / 4;          // 4 tokens per block
    tte_main<<<grid, 256>>>(x, out, ntok);
}

// round 10
// speedup vs baseline: 1.2562x; 1.1766x over previous
#include <cuda_runtime.h>
#include <cstdint>

// TensorizedEmbedding: vocab=32000=(8,10,20,20), out=768=(4,4,6,8), ranks (1,16,16,16,1)
//   a = idx/400 in [0,80)   -> T01[a] : [16 r2][16 m01 pair-permuted] (80 KB)
//   b = idx%400 in [0,400)  -> T23[b] : [16 r2][48 m23] linear        (1.2 MB, L2)
// Main: 256 threads = 8 warps = 8 tokens (warp per token). T23 staged to smem
// linearly (no repack). Lane tile 2 rows x 12 cols = 24 acc; per r2:
// 1 LDG.64 (T01 row pair) + 3 LDS.128 -> 24 FMA (1:6 load:FMA, ~0 repack ALU).

__device__ __align__(16) float g_T01[80 * 256];   // [a][r2][m01pp], m01pp=(m&7)*2+(m>>3)
__device__ __align__(16) float g_T23[400 * 768];  // [b][r2][m23] linear

#define TOK_PER_BLK 8
#define SMEM_STRIDE 784   // 768 + 16 pad floats

// ---------------------------------------------------------------------------
__global__ void precompute_tables(const float* __restrict__ core0,
                                  const float* __restrict__ core1,
                                  const float* __restrict__ core2,
                                  const float* __restrict__ core3) {
    int i = blockIdx.x * blockDim.x + threadIdx.x;
    if (i < 400 * 768) {
        // T23[b][r2][m23] = sum_r3 core2[r2][d2][m2][r3] * core3[r3][d3][m3]
        int b = i / 768;
        int e = i - b * 768;
        int r2  = e / 48;
        int m23 = e - r2 * 48;
        int m2 = m23 >> 3, m3 = m23 & 7;
        int d2 = b / 20;
        int d3 = b - d2 * 20;
        float s = 0.f;
#pragma unroll
        for (int r3 = 0; r3 < 16; ++r3) {
            float c2 = __ldg(core2 + (((r2 * 20 + d2) * 6 + m2) * 16 + r3));
            float c3 = __ldg(core3 + ((r3 * 20 + d3) * 8 + m3));
            s = fmaf(c2, c3, s);
        }
        g_T23[i] = s;
    } else if (i < 400 * 768 + 80 * 256) {
        // T01[a][r2][m01] = sum_r1 core0[0][d0][m0][r1] * core1[r1][d1][m1][r2]
        int j = i - 400 * 768;
        int a = j >> 8;
        int e = j & 255;
        int r2  = e & 15;
        int m01 = e >> 4;
        int m0 = m01 >> 2, m1 = m01 & 3;
        int d0 = a / 10;
        int d1 = a - d0 * 10;
        float s = 0.f;
#pragma unroll
        for (int r1 = 0; r1 < 16; ++r1) {
            float c0 = __ldg(core0 + ((d0 * 4 + m0) * 16 + r1));
            float c1 = __ldg(core1 + (((r1 * 10 + d1) * 4 + m1) * 16 + r2));
            s = fmaf(c0, c1, s);
        }
        int m01pp = ((m01 & 7) << 1) | (m01 >> 3);   // pair permutation: rows {r, r+8}
        g_T01[a * 256 + r2 * 16 + m01pp] = s;
    }
}

// ---------------------------------------------------------------------------
__global__ void __launch_bounds__(256)
tte_main(const int* __restrict__ x, float* __restrict__ out, int ntok) {
    __shared__ __align__(16) float sT23[TOK_PER_BLK * SMEM_STRIDE];  // ~24.5 KB
    __shared__ int s_a[TOK_PER_BLK];
    __shared__ int s_b[TOK_PER_BLK];

    int tid    = threadIdx.x;
    int t_base = blockIdx.x * TOK_PER_BLK;

    if (tid < TOK_PER_BLK) {
        int t = t_base + tid;
        int idxv = (t < ntok) ? __ldg(x + t) : 0;
        int a = idxv / 400;
        s_a[tid] = a;
        s_b[tid] = idxv - a * 400;
    }
    __syncthreads();

    // Stage all 8 token panels: 8 x 192 float4, linear copy.
    for (int k = tid; k < TOK_PER_BLK * 192; k += 256) {
        int lt = k / 192;
        int j  = k - lt * 192;
        ((float4*)(sT23 + lt * SMEM_STRIDE))[j] =
            __ldg((const float4*)(g_T23 + s_b[lt] * 768) + j);
    }
    __syncthreads();

    int warp = tid >> 5;
    int lane = tid & 31;
    int t    = t_base + warp;
    if (t >= ntok) return;

    int gr  = lane >> 2;    // 0..7: rows {gr, gr+8}
    int g23 = lane & 3;     // 0..3: cols 12*g23 .. +12

    const float2* __restrict__ p2 =
        (const float2*)(g_T01 + s_a[warp] * 256) + gr;   // index: r2*8 + gr
    const float* qs = sT23 + warp * SMEM_STRIDE + g23 * 12;

    float acc0[12], acc1[12];
#pragma unroll
    for (int k = 0; k < 12; ++k) { acc0[k] = 0.f; acc1[k] = 0.f; }

#pragma unroll
    for (int r2 = 0; r2 < 16; ++r2) {
        float2 p  = __ldg(p2 + r2 * 8);
        float4 q0 = *(const float4*)(qs + r2 * 48);
        float4 q1 = *(const float4*)(qs + r2 * 48 + 4);
        float4 q2 = *(const float4*)(qs + r2 * 48 + 8);
        float qq[12] = {q0.x, q0.y, q0.z, q0.w,
                        q1.x, q1.y, q1.z, q1.w,
                        q2.x, q2.y, q2.z, q2.w};
#pragma unroll
        for (int k = 0; k < 12; ++k) {
            acc0[k] = fmaf(p.x, qq[k], acc0[k]);
            acc1[k] = fmaf(p.y, qq[k], acc1[k]);
        }
    }

    // Stores: row gr (acc0) and row gr+8 (acc1); per round the warp writes
    // 8 rows x 48 cols = 1536B contiguous; 3 x STG.128 per lane per row.
    float* o0 = out + (size_t)t * 768 + gr * 48 + g23 * 12;
    float4* s0 = (float4*)o0;
    s0[0] = make_float4(acc0[0], acc0[1], acc0[2],  acc0[3]);
    s0[1] = make_float4(acc0[4], acc0[5], acc0[6],  acc0[7]);
    s0[2] = make_float4(acc0[8], acc0[9], acc0[10], acc0[11]);
    float4* s1 = (float4*)(o0 + 8 * 48);
    s1[0] = make_float4(acc1[0], acc1[1], acc1[2],  acc1[3]);
    s1[1] = make_float4(acc1[4], acc1[5], acc1[6],  acc1[7]);
    s1[2] = make_float4(acc1[8], acc1[9], acc1[10], acc1[11]);
}

// ---------------------------------------------------------------------------
extern "C" void kernel_launch(void* const* d_in, const int* in_sizes, int n_in,
                              void* d_out, int out_size) {
    const int*   x     = (const int*)d_in[0];
    const float* core0 = (const float*)d_in[1];
    const float* core1 = (const float*)d_in[2];
    const float* core2 = (const float*)d_in[3];
    const float* core3 = (const float*)d_in[4];
    float* out = (float*)d_out;

    int ntok = in_sizes[0];   // 32768

    int pre_total = 400 * 768 + 80 * 256;
    precompute_tables<<<(pre_total + 255) / 256, 256>>>(core0, core1, core2, core3);

    int grid = (ntok + TOK_PER_BLK - 1) / TOK_PER_BLK;
    tte_main<<<grid, 256>>>(x, out, ntok);
}